// round 11
// baseline (speedup 1.0000x reference)
#include <cuda_runtime.h>
#include <cuda_fp16.h>
#include <math.h>
#include <stdint.h>

#define BB 256
#define SS 256
#define DD 256
#define HH 4
#define DHH 64
#define LL 2
#define MM (BB*SS)          // 65536
#define FF (4*DD)           // 1024
#define QKVN 768

// ---------------- scratch (no malloc allowed) ----------------
__device__ float g_x  [ (size_t)MM*DD ];                     // fp32 residual
__device__ __align__(16) __half g_xt  [ (size_t)MM*DD ];     // half activations
__device__ __align__(16) __half g_qkv [ (size_t)MM*QKVN ];   // packed q|k|v
__device__ __align__(16) __half g_ctxt[ (size_t)MM*DD ];
__device__ __align__(16) __half g_ht  [ (size_t)MM*DD ];
__device__ __align__(16) __half g_midt[ (size_t)MM*FF ];
__device__ __align__(16) __half g_wt  [ (size_t)LL*786432 ]; // converted weights
__device__ float g_bqkv [ (size_t)LL*QKVN ];                 // concat qkv bias

// ---------------- helpers ----------------
__device__ __forceinline__ float block_sum_256(float v, float* sh) {
    int tid = threadIdx.x;
    sh[tid] = v; __syncthreads();
    #pragma unroll
    for (int s = 128; s > 0; s >>= 1) {
        if (tid < s) sh[tid] += sh[tid + s];
        __syncthreads();
    }
    float r = sh[0];
    __syncthreads();
    return r;
}

__device__ __forceinline__ void mma_f16(float* d, const uint32_t* a, const uint32_t* b) {
    asm volatile("mma.sync.aligned.m16n8k16.row.col.f32.f16.f16.f32 "
        "{%0,%1,%2,%3}, {%4,%5,%6,%7}, {%8,%9}, {%0,%1,%2,%3};"
        : "+f"(d[0]), "+f"(d[1]), "+f"(d[2]), "+f"(d[3])
        : "r"(a[0]), "r"(a[1]), "r"(a[2]), "r"(a[3]), "r"(b[0]), "r"(b[1]));
}

__device__ __forceinline__ void ldsm_x4(uint32_t* d, uint32_t a) {
    asm volatile("ldmatrix.sync.aligned.m8n8.x4.shared.b16 {%0,%1,%2,%3}, [%4];"
        : "=r"(d[0]), "=r"(d[1]), "=r"(d[2]), "=r"(d[3]) : "r"(a));
}
__device__ __forceinline__ void ldsm_x4_t(uint32_t* d, uint32_t a) {
    asm volatile("ldmatrix.sync.aligned.m8n8.x4.trans.shared.b16 {%0,%1,%2,%3}, [%4];"
        : "=r"(d[0]), "=r"(d[1]), "=r"(d[2]), "=r"(d[3]) : "r"(a));
}

__device__ __forceinline__ void cp_async16(uint32_t s, const void* g) {
    asm volatile("cp.async.cg.shared.global [%0], [%1], 16;" :: "r"(s), "l"(g));
}
__device__ __forceinline__ void cp_commit() { asm volatile("cp.async.commit_group;"); }
template<int N_> __device__ __forceinline__ void cp_wait() {
    asm volatile("cp.async.wait_group %0;" :: "n"(N_));
}

__device__ __forceinline__ uint32_t smem_u32(const void* p) {
    uint32_t a;
    asm("{ .reg .u64 t; cvta.to.shared.u64 t, %1; cvt.u32.u64 %0, t; }" : "=r"(a) : "l"(p));
    return a;
}

// ---------------- batched weight convert ----------------
__global__ void conv_all(const float* __restrict__ Wq, const float* __restrict__ Wk,
                         const float* __restrict__ Wv, const float* __restrict__ Wo,
                         const float* __restrict__ W1, const float* __restrict__ W2,
                         __half* __restrict__ wt) {
    size_t idx = (size_t)blockIdx.x * 256 + threadIdx.x;
    if (idx >= (size_t)LL * 786432) return;
    int l = (int)(idx / 786432);
    int off = (int)(idx % 786432);
    const float* src; int N, K, local;
    if (off < 196608) {
        int w = off >> 16; local = off & 65535; K = 256; N = 256;
        src = (w == 0 ? Wq : (w == 1 ? Wk : Wv)) + (size_t)l * 65536;
    } else if (off < 262144) {
        local = off - 196608; K = 256; N = 256; src = Wo + (size_t)l * 65536;
    } else if (off < 524288) {
        local = off - 262144; K = 256; N = 1024; src = W1 + (size_t)l * 262144;
    } else {
        local = off - 524288; K = 1024; N = 256; src = W2 + (size_t)l * 262144;
    }
    int n = local / K, k = local % K;
    wt[idx] = __float2half_rn(src[(size_t)k * N + n]);
}

__global__ void concat_bias(const float* __restrict__ bq, const float* __restrict__ bk,
                            const float* __restrict__ bv, float* __restrict__ dst) {
    int l = blockIdx.y;
    int i = blockIdx.x * 256 + threadIdx.x;
    float v = (i < 256) ? bq[l * 256 + i]
            : (i < 512) ? bk[l * 256 + i - 256]
                        : bv[l * 256 + i - 512];
    dst[l * QKVN + i] = v;
}

// ---------------- embedding + LN ----------------
__global__ void embed_ln_kernel(const int* __restrict__ ids,
                                const float* __restrict__ item_emb,
                                const float* __restrict__ pos_emb,
                                float* __restrict__ x, __half* __restrict__ xt,
                                float* __restrict__ out) {
    __shared__ float sh[256];
    int row = blockIdx.x;
    int s   = row & (SS - 1);
    int tid = threadIdx.x;
    int id  = ids[row];
    float v = item_emb[(size_t)id * DD + tid] + pos_emb[s * DD + tid];
    float mu  = block_sum_256(v, sh) * (1.0f / DD);
    float d   = v - mu;
    float var = block_sum_256(d * d, sh) * (1.0f / DD);
    float o   = d * rsqrtf(var + 1e-5f);
    size_t idx = (size_t)row * DD + tid;
    x[idx] = o;
    out[idx] = o;
    xt[idx] = __float2half_rn(o);
}

// =====================================================================
// FP16 GEMM v2: CTA tile 128x256, BK=64, 8 warps of 64x64 (2M x 4N),
// 3-stage cp.async, 144B row stride.
// EPI: 0 = bias (half out)
//      1 = bias + GELU (half out)
//      2 = LN(acc + bias + resid)  -> Ch half   (Wo path)
//      3 = LN(acc + bias)          -> x, xt, total (FF2 path)
// EPI 2/3 require N==256, gridDim.x==1.
// =====================================================================
#define G2_ASZ   18432              // A region bytes per stage (128*144)
#define G2_STG   55296              // stage stride (A + B 256*144)
#define G2_SMEM  (3 * G2_STG)       // 165888

template<int EPI>
__global__ void __launch_bounds__(256, 1)
hgemm2(const __half* __restrict__ A, const __half* __restrict__ Bt,
       const float* __restrict__ bias, const float* __restrict__ resid,
       __half* __restrict__ Ch, float* __restrict__ x,
       __half* __restrict__ xt, float* __restrict__ total,
       int K, int N)
{
    extern __shared__ char smem[];
    const uint32_t sb = smem_u32(smem);

    const int tid  = threadIdx.x;
    const int lane = tid & 31;
    const int wid  = tid >> 5;
    const int warp_m = wid & 1;
    const int warp_n = wid >> 1;                 // 0..3
    const int r  = lane >> 2;
    const int cf = lane & 3;
    const int quad = lane >> 3, li = lane & 7;

    const int bm = blockIdx.y << 7;
    const int bn = blockIdx.x << 8;

    // ---- loaders ----
    // A: 128 rows x 128B -> 256 x 64B chunks, 1/thread (4 cp16)
    const int arow = tid >> 1;
    const int ahalf = (tid & 1) * 64;            // byte offset in row
    const __half* Ag = A + (size_t)(bm + arow) * K + (ahalf >> 1);
    const uint32_t sA = sb + arow * 144 + ahalf;
    // B: 256 rows x 128B -> 512 x 64B chunks, 2/thread (8 cp16)
    const int br0 = tid >> 1,           bh0 = ahalf;
    const int br1 = (tid + 256) >> 1,   bh1 = ahalf;
    const __half* Bg0 = Bt + (size_t)(bn + br0) * K + (bh0 >> 1);
    const __half* Bg1 = Bt + (size_t)(bn + br1) * K + (bh1 >> 1);
    const uint32_t sB0 = sb + G2_ASZ + br0 * 144 + bh0;
    const uint32_t sB1 = sb + G2_ASZ + br1 * 144 + bh1;

    const int nsteps = K >> 6;

    #pragma unroll
    for (int s = 0; s < 2; s++) {
        const uint32_t o = s * G2_STG;
        #pragma unroll
        for (int g = 0; g < 4; g++) {
            cp_async16(sA  + o + g * 16, Ag  + s * 64 + g * 8);
            cp_async16(sB0 + o + g * 16, Bg0 + s * 64 + g * 8);
            cp_async16(sB1 + o + g * 16, Bg1 + s * 64 + g * 8);
        }
        cp_commit();
    }

    const uint32_t aoff = (uint32_t)((warp_m * 64 + ((quad & 1) << 3) + li) * 144
                                     + ((quad >> 1) << 4));
    const uint32_t boff = (uint32_t)(G2_ASZ + (warp_n * 64 + ((quad & 2) ? 8 : 0) + li) * 144
                                     + ((quad & 1) << 4));

    float acc[4][8][4];
    #pragma unroll
    for (int i = 0; i < 4; i++)
        #pragma unroll
        for (int j = 0; j < 8; j++)
            #pragma unroll
            for (int p = 0; p < 4; p++) acc[i][j][p] = 0.0f;

    for (int s = 0; s < nsteps; s++) {
        if (s + 1 < nsteps) cp_wait<1>(); else cp_wait<0>();
        __syncthreads();
        if (s + 2 < nsteps) {
            const uint32_t o = ((s + 2) % 3) * G2_STG;
            #pragma unroll
            for (int g = 0; g < 4; g++) {
                cp_async16(sA  + o + g * 16, Ag  + (s + 2) * 64 + g * 8);
                cp_async16(sB0 + o + g * 16, Bg0 + (s + 2) * 64 + g * 8);
                cp_async16(sB1 + o + g * 16, Bg1 + (s + 2) * 64 + g * 8);
            }
            cp_commit();
        }
        const uint32_t stg = sb + (s % 3) * G2_STG;

        #pragma unroll
        for (int ks = 0; ks < 4; ks++) {
            uint32_t af[4][4];
            #pragma unroll
            for (int i = 0; i < 4; i++)
                ldsm_x4(af[i], stg + aoff + i * 2304 + ks * 32);
            #pragma unroll
            for (int j2 = 0; j2 < 4; j2++) {
                uint32_t bf[4];
                ldsm_x4(bf, stg + boff + j2 * 2304 + ks * 32);
                #pragma unroll
                for (int i = 0; i < 4; i++) {
                    mma_f16(acc[i][2 * j2],     af[i], bf);
                    mma_f16(acc[i][2 * j2 + 1], af[i], bf + 2);
                }
            }
        }
    }

    if (EPI <= 1) {
        // ---- plain epilogue ----
        #pragma unroll
        for (int i = 0; i < 4; i++) {
            #pragma unroll
            for (int j = 0; j < 8; j++) {
                int gr0 = bm + warp_m * 64 + i * 16 + r;
                int gc  = bn + warp_n * 64 + j * 8 + cf * 2;
                float v00 = acc[i][j][0] + bias[gc];
                float v01 = acc[i][j][1] + bias[gc + 1];
                float v10 = acc[i][j][2] + bias[gc];
                float v11 = acc[i][j][3] + bias[gc + 1];
                if (EPI == 1) {
                    v00 = 0.5f * v00 * (1.0f + erff(v00 * 0.7071067811865476f));
                    v01 = 0.5f * v01 * (1.0f + erff(v01 * 0.7071067811865476f));
                    v10 = 0.5f * v10 * (1.0f + erff(v10 * 0.7071067811865476f));
                    v11 = 0.5f * v11 * (1.0f + erff(v11 * 0.7071067811865476f));
                }
                *(__half2*)(Ch + (size_t)gr0 * N + gc)       = __floats2half2_rn(v00, v01);
                *(__half2*)(Ch + (size_t)(gr0 + 8) * N + gc) = __floats2half2_rn(v10, v11);
            }
        }
        return;
    }

    // ---- LN epilogue (N == 256, bn == 0, full rows in CTA) ----
    __syncthreads();   // mainloop smem reads done -> alias reduction buffers
    float* redA = (float*)smem;            // [128][4]
    float* redB = (float*)(smem + 2048);   // [128][4]

    // bias (+resid)
    #pragma unroll
    for (int i = 0; i < 4; i++) {
        int gr0 = bm + warp_m * 64 + i * 16 + r;
        #pragma unroll
        for (int j = 0; j < 8; j++) {
            int gc = warp_n * 64 + j * 8 + cf * 2;
            float b0 = bias[gc], b1 = bias[gc + 1];
            acc[i][j][0] += b0; acc[i][j][1] += b1;
            acc[i][j][2] += b0; acc[i][j][3] += b1;
            if (EPI == 2) {
                acc[i][j][0] += resid[(size_t)gr0 * 256 + gc];
                acc[i][j][1] += resid[(size_t)gr0 * 256 + gc + 1];
                acc[i][j][2] += resid[(size_t)(gr0 + 8) * 256 + gc];
                acc[i][j][3] += resid[(size_t)(gr0 + 8) * 256 + gc + 1];
            }
        }
    }

    // pass 1: mean
    #pragma unroll
    for (int i = 0; i < 4; i++) {
        float s_lo = 0.0f, s_hi = 0.0f;
        #pragma unroll
        for (int j = 0; j < 8; j++) {
            s_lo += acc[i][j][0] + acc[i][j][1];
            s_hi += acc[i][j][2] + acc[i][j][3];
        }
        s_lo += __shfl_xor_sync(0xFFFFFFFFu, s_lo, 1);
        s_lo += __shfl_xor_sync(0xFFFFFFFFu, s_lo, 2);
        s_hi += __shfl_xor_sync(0xFFFFFFFFu, s_hi, 1);
        s_hi += __shfl_xor_sync(0xFFFFFFFFu, s_hi, 2);
        if (cf == 0) {
            int rl = warp_m * 64 + i * 16 + r;
            redA[rl * 4 + warp_n]       = s_lo;
            redA[(rl + 8) * 4 + warp_n] = s_hi;
        }
    }
    __syncthreads();
    float mu[4][2];
    #pragma unroll
    for (int i = 0; i < 4; i++) {
        int rl = warp_m * 64 + i * 16 + r;
        float a = 0.0f, b = 0.0f;
        #pragma unroll
        for (int w = 0; w < 4; w++) { a += redA[rl * 4 + w]; b += redA[(rl + 8) * 4 + w]; }
        mu[i][0] = a * (1.0f / 256.0f);
        mu[i][1] = b * (1.0f / 256.0f);
    }

    // pass 2: variance
    #pragma unroll
    for (int i = 0; i < 4; i++) {
        float s_lo = 0.0f, s_hi = 0.0f;
        #pragma unroll
        for (int j = 0; j < 8; j++) {
            float d0 = acc[i][j][0] - mu[i][0], d1 = acc[i][j][1] - mu[i][0];
            float d2 = acc[i][j][2] - mu[i][1], d3 = acc[i][j][3] - mu[i][1];
            s_lo += d0 * d0 + d1 * d1;
            s_hi += d2 * d2 + d3 * d3;
        }
        s_lo += __shfl_xor_sync(0xFFFFFFFFu, s_lo, 1);
        s_lo += __shfl_xor_sync(0xFFFFFFFFu, s_lo, 2);
        s_hi += __shfl_xor_sync(0xFFFFFFFFu, s_hi, 1);
        s_hi += __shfl_xor_sync(0xFFFFFFFFu, s_hi, 2);
        if (cf == 0) {
            int rl = warp_m * 64 + i * 16 + r;
            redB[rl * 4 + warp_n]       = s_lo;
            redB[(rl + 8) * 4 + warp_n] = s_hi;
        }
    }
    __syncthreads();

    #pragma unroll
    for (int i = 0; i < 4; i++) {
        int rl = warp_m * 64 + i * 16 + r;
        float a = 0.0f, b = 0.0f;
        #pragma unroll
        for (int w = 0; w < 4; w++) { a += redB[rl * 4 + w]; b += redB[(rl + 8) * 4 + w]; }
        float rs_lo = rsqrtf(a * (1.0f / 256.0f) + 1e-5f);
        float rs_hi = rsqrtf(b * (1.0f / 256.0f) + 1e-5f);
        int gr0 = bm + rl;
        #pragma unroll
        for (int j = 0; j < 8; j++) {
            int gc = warp_n * 64 + j * 8 + cf * 2;
            float o00 = (acc[i][j][0] - mu[i][0]) * rs_lo;
            float o01 = (acc[i][j][1] - mu[i][0]) * rs_lo;
            float o10 = (acc[i][j][2] - mu[i][1]) * rs_hi;
            float o11 = (acc[i][j][3] - mu[i][1]) * rs_hi;
            if (EPI == 2) {
                *(__half2*)(Ch + (size_t)gr0 * 256 + gc)       = __floats2half2_rn(o00, o01);
                *(__half2*)(Ch + (size_t)(gr0 + 8) * 256 + gc) = __floats2half2_rn(o10, o11);
            } else {
                size_t i0 = (size_t)gr0 * 256 + gc;
                size_t i1 = (size_t)(gr0 + 8) * 256 + gc;
                *(float2*)(x + i0) = make_float2(o00, o01);
                *(float2*)(x + i1) = make_float2(o10, o11);
                float2 t0 = *(float2*)(total + i0);
                float2 t1 = *(float2*)(total + i1);
                t0.x += o00; t0.y += o01; t1.x += o10; t1.y += o11;
                *(float2*)(total + i0) = t0;
                *(float2*)(total + i1) = t1;
                *(__half2*)(xt + i0) = __floats2half2_rn(o00, o01);
                *(__half2*)(xt + i1) = __floats2half2_rn(o10, o11);
            }
        }
    }
}

// =====================================================================
// Fused FP16 attention (packed qkv). V cp.async-prefetched during softmax.
// =====================================================================
#define ATTN_SMEM_BYTES 81920

__global__ void __launch_bounds__(256, 2)
attn_fused(const __half* __restrict__ qkv, const int* __restrict__ ids,
           __half* __restrict__ ctxt)
{
    extern __shared__ char sm[];
    char* Qs = sm;                    // 9216 B
    char* KV = sm + 9216;             // 36864 B
    char* Ph = sm + 46080;            // 33792 B
    float* red   = (float*)(sm + 79872);
    int*   ids_s = (int*)(sm + 80896);

    const int tid  = threadIdx.x;
    const int lane = tid & 31;
    const int wid  = tid >> 5;
    const int r  = lane >> 2;
    const int cf = lane & 3;
    const int quad = lane >> 3, li = lane & 7;

    const int qb = blockIdx.x;
    const int bh = blockIdx.y;
    const int b  = bh >> 2, h = bh & 3;

    const __half* Qg = qkv + ((size_t)b * SS + qb * 64) * QKVN + h * DHH;
    const __half* Kg = qkv + (size_t)b * SS * QKVN + 256 + h * DHH;
    const __half* Vg = qkv + (size_t)b * SS * QKVN + 512 + h * DHH;
    __half* Cg = ctxt + (size_t)b * SS * DD + h * DHH + (size_t)qb * 64 * DD;
    const int* idb = ids + b * SS;

    ids_s[tid] = idb[tid];

    {
        int row = tid >> 2, c = (tid & 3) * 32;
        const __half* src = Qg + (size_t)row * QKVN + (c >> 1);
        *(float4*)(Qs + row * 144 + c)      = *(const float4*)(src);
        *(float4*)(Qs + row * 144 + c + 16) = *(const float4*)(src + 8);
    }
    #pragma unroll
    for (int rp = 0; rp < 4; rp++) {
        int row = (tid >> 2) + rp * 64, c = (tid & 3) * 32;
        const __half* src = Kg + (size_t)row * QKVN + (c >> 1);
        *(float4*)(KV + row * 144 + c)      = *(const float4*)(src);
        *(float4*)(KV + row * 144 + c + 16) = *(const float4*)(src + 8);
    }
    __syncthreads();

    const int wm = wid & 3, wn = wid >> 2;
    const uint32_t sbQ = smem_u32(Qs);
    const uint32_t sbK = smem_u32(KV);
    const uint32_t sbP = smem_u32(Ph);

    float acc[16][4];
    #pragma unroll
    for (int j = 0; j < 16; j++)
        #pragma unroll
        for (int p = 0; p < 4; p++) acc[j][p] = 0.0f;

    {
        uint32_t qa[4][4];
        const uint32_t qoff = sbQ + (wm * 16 + ((quad & 1) << 3) + li) * 144
                              + ((quad >> 1) << 4);
        #pragma unroll
        for (int ks = 0; ks < 4; ks++) ldsm_x4(qa[ks], qoff + ks * 32);

        const uint32_t koff = sbK + (((quad & 2) ? 8 : 0) + li) * 144 + ((quad & 1) << 4);
        #pragma unroll
        for (int j2 = 0; j2 < 8; j2++) {
            #pragma unroll
            for (int ks = 0; ks < 4; ks++) {
                uint32_t bf[4];
                ldsm_x4(bf, koff + (wn * 128 + j2 * 16) * 144 + ks * 32);
                mma_f16(acc[2 * j2],     qa[ks], bf);
                mma_f16(acc[2 * j2 + 1], qa[ks], bf + 2);
            }
        }
    }

    {
        const int row_lo = qb * 64 + wm * 16 + r;
        const int row_hi = row_lo + 8;
        float mlo = -1e30f, mhi = -1e30f;
        #pragma unroll
        for (int j = 0; j < 16; j++) {
            int gc = wn * 128 + j * 8 + cf * 2;
            bool ok0 = ids_s[gc] > 0, ok1 = ids_s[gc + 1] > 0;
            acc[j][0] = acc[j][0] * 0.125f + ((ok0 && gc     <= row_lo) ? 0.0f : -10000.0f);
            acc[j][1] = acc[j][1] * 0.125f + ((ok1 && gc + 1 <= row_lo) ? 0.0f : -10000.0f);
            acc[j][2] = acc[j][2] * 0.125f + ((ok0 && gc     <= row_hi) ? 0.0f : -10000.0f);
            acc[j][3] = acc[j][3] * 0.125f + ((ok1 && gc + 1 <= row_hi) ? 0.0f : -10000.0f);
            mlo = fmaxf(mlo, fmaxf(acc[j][0], acc[j][1]));
            mhi = fmaxf(mhi, fmaxf(acc[j][2], acc[j][3]));
        }
        mlo = fmaxf(mlo, __shfl_xor_sync(0xFFFFFFFFu, mlo, 1));
        mlo = fmaxf(mlo, __shfl_xor_sync(0xFFFFFFFFu, mlo, 2));
        mhi = fmaxf(mhi, __shfl_xor_sync(0xFFFFFFFFu, mhi, 1));
        mhi = fmaxf(mhi, __shfl_xor_sync(0xFFFFFFFFu, mhi, 2));
        if (cf == 0) {
            red[(wm * 16 + r) * 2 + wn]     = mlo;
            red[(wm * 16 + 8 + r) * 2 + wn] = mhi;
        }
        __syncthreads();   // score MMAs done -> K buffer dead

        {
            int row0 = tid >> 2, c = (tid & 3) * 32;
            #pragma unroll
            for (int rp = 0; rp < 4; rp++) {
                int row = row0 + rp * 64;
                const __half* src = Vg + (size_t)row * QKVN + (c >> 1);
                cp_async16(sbK + row * 144 + c,      src);
                cp_async16(sbK + row * 144 + c + 16, src + 8);
            }
            cp_commit();
        }

        float Mlo = fmaxf(red[(wm * 16 + r) * 2],     red[(wm * 16 + r) * 2 + 1]);
        float Mhi = fmaxf(red[(wm * 16 + 8 + r) * 2], red[(wm * 16 + 8 + r) * 2 + 1]);

        float slo = 0.0f, shi = 0.0f;
        #pragma unroll
        for (int j = 0; j < 16; j++) {
            acc[j][0] = __expf(acc[j][0] - Mlo);
            acc[j][1] = __expf(acc[j][1] - Mlo);
            acc[j][2] = __expf(acc[j][2] - Mhi);
            acc[j][3] = __expf(acc[j][3] - Mhi);
            slo += acc[j][0] + acc[j][1];
            shi += acc[j][2] + acc[j][3];
        }
        slo += __shfl_xor_sync(0xFFFFFFFFu, slo, 1);
        slo += __shfl_xor_sync(0xFFFFFFFFu, slo, 2);
        shi += __shfl_xor_sync(0xFFFFFFFFu, shi, 1);
        shi += __shfl_xor_sync(0xFFFFFFFFu, shi, 2);
        if (cf == 0) {
            red[128 + (wm * 16 + r) * 2 + wn]     = slo;
            red[128 + (wm * 16 + 8 + r) * 2 + wn] = shi;
        }
        __syncthreads();
        float inv_lo = 1.0f / (red[128 + (wm * 16 + r) * 2]     + red[128 + (wm * 16 + r) * 2 + 1]);
        float inv_hi = 1.0f / (red[128 + (wm * 16 + 8 + r) * 2] + red[128 + (wm * 16 + 8 + r) * 2 + 1]);

        #pragma unroll
        for (int j = 0; j < 16; j++) {
            int gc = wn * 128 + j * 8 + cf * 2;
            *(__half2*)(Ph + (wm * 16 + r) * 528 + gc * 2) =
                __floats2half2_rn(acc[j][0] * inv_lo, acc[j][1] * inv_lo);
            *(__half2*)(Ph + (wm * 16 + 8 + r) * 528 + gc * 2) =
                __floats2half2_rn(acc[j][2] * inv_hi, acc[j][3] * inv_hi);
        }
    }
    cp_wait<0>();
    __syncthreads();

    {
        float acc2[4][4];
        #pragma unroll
        for (int j = 0; j < 4; j++)
            #pragma unroll
            for (int p = 0; p < 4; p++) acc2[j][p] = 0.0f;

        const uint32_t poff = sbP + (wm * 16 + ((quad & 1) << 3) + li) * 528
                              + ((quad >> 1) << 4);
        const int vrow_l = ((quad & 1) << 3) + li;
        const int vcol_l = ((quad >> 1) << 3);

        #pragma unroll 4
        for (int ks = 0; ks < 16; ks++) {
            uint32_t pa[4];
            ldsm_x4(pa, poff + ks * 32);
            #pragma unroll
            for (int j2 = 0; j2 < 2; j2++) {
                uint32_t vb[4];
                ldsm_x4_t(vb, sbK + (ks * 16 + vrow_l) * 144
                              + (wn * 32 + j2 * 16 + vcol_l) * 2);
                mma_f16(acc2[2 * j2],     pa, vb);
                mma_f16(acc2[2 * j2 + 1], pa, vb + 2);
            }
        }

        #pragma unroll
        for (int j = 0; j < 4; j++) {
            int lrow = wm * 16 + r;
            int gc   = wn * 32 + j * 8 + cf * 2;
            *(__half2*)(Cg + (size_t)lrow * DD + gc) =
                __floats2half2_rn(acc2[j][0], acc2[j][1]);
            *(__half2*)(Cg + (size_t)(lrow + 8) * DD + gc) =
                __floats2half2_rn(acc2[j][2], acc2[j][3]);
        }
    }
}

// ---------------- host orchestration ----------------
extern "C" void kernel_launch(void* const* d_in, const int* in_sizes, int n_in,
                              void* d_out, int out_size) {
    const int*   ids      = (const int*)  d_in[0];
    const float* item_emb = (const float*)d_in[1];
    const float* pos_emb  = (const float*)d_in[2];
    const float* Wq = (const float*)d_in[3];
    const float* bq = (const float*)d_in[4];
    const float* Wk = (const float*)d_in[5];
    const float* bk = (const float*)d_in[6];
    const float* Wv = (const float*)d_in[7];
    const float* bv = (const float*)d_in[8];
    const float* Wo = (const float*)d_in[9];
    const float* bo = (const float*)d_in[10];
    const float* W1 = (const float*)d_in[11];
    const float* b1 = (const float*)d_in[12];
    const float* W2 = (const float*)d_in[13];
    const float* b2 = (const float*)d_in[14];
    float* out = (float*)d_out;

    float *x, *bqkv;
    __half *xt, *qkv, *ctxt, *ht, *midt, *wt;
    cudaGetSymbolAddress((void**)&x,    g_x);
    cudaGetSymbolAddress((void**)&xt,   g_xt);
    cudaGetSymbolAddress((void**)&qkv,  g_qkv);
    cudaGetSymbolAddress((void**)&ctxt, g_ctxt);
    cudaGetSymbolAddress((void**)&ht,   g_ht);
    cudaGetSymbolAddress((void**)&midt, g_midt);
    cudaGetSymbolAddress((void**)&wt,   g_wt);
    cudaGetSymbolAddress((void**)&bqkv, g_bqkv);

    cudaFuncSetAttribute(attn_fused, cudaFuncAttributeMaxDynamicSharedMemorySize,
                         ATTN_SMEM_BYTES);
    cudaFuncSetAttribute(hgemm2<0>, cudaFuncAttributeMaxDynamicSharedMemorySize, G2_SMEM);
    cudaFuncSetAttribute(hgemm2<1>, cudaFuncAttributeMaxDynamicSharedMemorySize, G2_SMEM);
    cudaFuncSetAttribute(hgemm2<2>, cudaFuncAttributeMaxDynamicSharedMemorySize, G2_SMEM);
    cudaFuncSetAttribute(hgemm2<3>, cudaFuncAttributeMaxDynamicSharedMemorySize, G2_SMEM);

    conv_all<<<(LL * 786432 + 255) / 256, 256>>>(Wq, Wk, Wv, Wo, W1, W2, wt);
    {
        dim3 g(3, LL);
        concat_bias<<<g, 256>>>(bq, bk, bv, bqkv);
    }
    embed_ln_kernel<<<MM, 256>>>(ids, item_emb, pos_emb, x, xt, out);

    dim3 gQKV(QKVN / 256, MM / 128);    // (3, 512)
    dim3 gFF1(FF / 256, MM / 128);      // (4, 512)
    dim3 gLN(1, MM / 128);              // (1, 512)
    dim3 gAttn(SS / 64, BB * HH);       // (4, 1024)

    for (int l = 0; l < LL; l++) {
        __half* base = wt + (size_t)l * 786432;
        const __half* Wqkvt = base;
        const __half* Wot   = base + 196608;
        const __half* W1t   = base + 262144;
        const __half* W2t   = base + 524288;

        hgemm2<0><<<gQKV, 256, G2_SMEM>>>(xt, Wqkvt, bqkv + l * QKVN, nullptr,
                                          qkv, nullptr, nullptr, nullptr, DD, QKVN);

        attn_fused<<<gAttn, 256, ATTN_SMEM_BYTES>>>(qkv, ids, ctxt);

        hgemm2<2><<<gLN, 256, G2_SMEM>>>(ctxt, Wot, bo + l * DD, x,
                                         ht, nullptr, nullptr, nullptr, DD, DD);

        hgemm2<1><<<gFF1, 256, G2_SMEM>>>(ht, W1t, b1 + l * FF, nullptr,
                                          midt, nullptr, nullptr, nullptr, DD, FF);

        hgemm2<3><<<gLN, 256, G2_SMEM>>>(midt, W2t, b2 + l * DD, nullptr,
                                         nullptr, x, xt, out, FF, DD);
    }
}

// round 13
// speedup vs baseline: 1.1546x; 1.1546x over previous
#include <cuda_runtime.h>
#include <cuda_fp16.h>
#include <math.h>
#include <stdint.h>

#define BB 256
#define SS 256
#define DD 256
#define HH 4
#define DHH 64
#define LL 2
#define MM (BB*SS)          // 65536
#define FF (4*DD)           // 1024
#define QKVN 768

// ---------------- scratch (no malloc allowed) ----------------
__device__ float g_x  [ (size_t)MM*DD ];                     // fp32 residual
__device__ __align__(16) __half g_xt  [ (size_t)MM*DD ];     // half activations
__device__ __align__(16) __half g_qkv [ (size_t)MM*QKVN ];   // packed q|k|v
__device__ __align__(16) __half g_ctxt[ (size_t)MM*DD ];
__device__ __align__(16) __half g_ht  [ (size_t)MM*DD ];
__device__ __align__(16) __half g_midt[ (size_t)MM*FF ];
__device__ __align__(16) __half g_wt  [ (size_t)LL*786432 ]; // converted weights
__device__ float g_bqkv [ (size_t)LL*QKVN ];                 // concat qkv bias

// ---------------- helpers ----------------
__device__ __forceinline__ float block_sum_256(float v, float* sh) {
    int tid = threadIdx.x;
    sh[tid] = v; __syncthreads();
    #pragma unroll
    for (int s = 128; s > 0; s >>= 1) {
        if (tid < s) sh[tid] += sh[tid + s];
        __syncthreads();
    }
    float r = sh[0];
    __syncthreads();
    return r;
}

__device__ __forceinline__ void mma_f16(float* d, const uint32_t* a, const uint32_t* b) {
    asm volatile("mma.sync.aligned.m16n8k16.row.col.f32.f16.f16.f32 "
        "{%0,%1,%2,%3}, {%4,%5,%6,%7}, {%8,%9}, {%0,%1,%2,%3};"
        : "+f"(d[0]), "+f"(d[1]), "+f"(d[2]), "+f"(d[3])
        : "r"(a[0]), "r"(a[1]), "r"(a[2]), "r"(a[3]), "r"(b[0]), "r"(b[1]));
}

__device__ __forceinline__ void ldsm_x4(uint32_t* d, uint32_t a) {
    asm volatile("ldmatrix.sync.aligned.m8n8.x4.shared.b16 {%0,%1,%2,%3}, [%4];"
        : "=r"(d[0]), "=r"(d[1]), "=r"(d[2]), "=r"(d[3]) : "r"(a));
}
__device__ __forceinline__ void ldsm_x4_t(uint32_t* d, uint32_t a) {
    asm volatile("ldmatrix.sync.aligned.m8n8.x4.trans.shared.b16 {%0,%1,%2,%3}, [%4];"
        : "=r"(d[0]), "=r"(d[1]), "=r"(d[2]), "=r"(d[3]) : "r"(a));
}

__device__ __forceinline__ void cp_async16(uint32_t s, const void* g) {
    asm volatile("cp.async.cg.shared.global [%0], [%1], 16;" :: "r"(s), "l"(g));
}
__device__ __forceinline__ void cp_commit() { asm volatile("cp.async.commit_group;"); }
template<int N_> __device__ __forceinline__ void cp_wait() {
    asm volatile("cp.async.wait_group %0;" :: "n"(N_));
}

__device__ __forceinline__ uint32_t smem_u32(const void* p) {
    uint32_t a;
    asm("{ .reg .u64 t; cvta.to.shared.u64 t, %1; cvt.u32.u64 %0, t; }" : "=r"(a) : "l"(p));
    return a;
}

// ---------------- batched weight convert ----------------
__global__ void conv_all(const float* __restrict__ Wq, const float* __restrict__ Wk,
                         const float* __restrict__ Wv, const float* __restrict__ Wo,
                         const float* __restrict__ W1, const float* __restrict__ W2,
                         __half* __restrict__ wt) {
    size_t idx = (size_t)blockIdx.x * 256 + threadIdx.x;
    if (idx >= (size_t)LL * 786432) return;
    int l = (int)(idx / 786432);
    int off = (int)(idx % 786432);
    const float* src; int N, K, local;
    if (off < 196608) {
        int w = off >> 16; local = off & 65535; K = 256; N = 256;
        src = (w == 0 ? Wq : (w == 1 ? Wk : Wv)) + (size_t)l * 65536;
    } else if (off < 262144) {
        local = off - 196608; K = 256; N = 256; src = Wo + (size_t)l * 65536;
    } else if (off < 524288) {
        local = off - 262144; K = 256; N = 1024; src = W1 + (size_t)l * 262144;
    } else {
        local = off - 524288; K = 1024; N = 256; src = W2 + (size_t)l * 262144;
    }
    int n = local / K, k = local % K;
    wt[idx] = __float2half_rn(src[(size_t)k * N + n]);
}

__global__ void concat_bias(const float* __restrict__ bq, const float* __restrict__ bk,
                            const float* __restrict__ bv, float* __restrict__ dst) {
    int l = blockIdx.y;
    int i = blockIdx.x * 256 + threadIdx.x;
    float v = (i < 256) ? bq[l * 256 + i]
            : (i < 512) ? bk[l * 256 + i - 256]
                        : bv[l * 256 + i - 512];
    dst[l * QKVN + i] = v;
}

// ---------------- embedding + LN ----------------
__global__ void embed_ln_kernel(const int* __restrict__ ids,
                                const float* __restrict__ item_emb,
                                const float* __restrict__ pos_emb,
                                float* __restrict__ x, __half* __restrict__ xt,
                                float* __restrict__ out) {
    __shared__ float sh[256];
    int row = blockIdx.x;
    int s   = row & (SS - 1);
    int tid = threadIdx.x;
    int id  = ids[row];
    float v = item_emb[(size_t)id * DD + tid] + pos_emb[s * DD + tid];
    float mu  = block_sum_256(v, sh) * (1.0f / DD);
    float d   = v - mu;
    float var = block_sum_256(d * d, sh) * (1.0f / DD);
    float o   = d * rsqrtf(var + 1e-5f);
    size_t idx = (size_t)row * DD + tid;
    x[idx] = o;
    out[idx] = o;
    xt[idx] = __float2half_rn(o);
}

// =====================================================================
// FP16 GEMM: 128x128 tile, BK=64, 3-stage cp.async, 8 warps (R10 config).
// =====================================================================
#define HGEMM_SMEM (3 * 36864)

template<int GELU>
__global__ void __launch_bounds__(256, 2)
hgemm(const __half* __restrict__ A, const __half* __restrict__ Bt,
      const float* __restrict__ bias, __half* __restrict__ C, int K, int N)
{
    extern __shared__ char smem[];
    const uint32_t sb = smem_u32(smem);

    const int tid  = threadIdx.x;
    const int lane = tid & 31;
    const int wid  = tid >> 5;
    const int warp_m = wid & 1;
    const int warp_n = wid >> 1;
    const int r  = lane >> 2;
    const int cf = lane & 3;
    const int quad = lane >> 3, li = lane & 7;

    const int bm = blockIdx.y << 7;
    const int bn = blockIdx.x << 7;

    const int lrow = tid >> 1;
    const int lcb  = (tid & 1) * 64;
    const __half* Ag = A  + (size_t)(bm + lrow) * K + (lcb >> 1);
    const __half* Bg = Bt + (size_t)(bn + lrow) * K + (lcb >> 1);
    const uint32_t sA = sb +         lrow * 144 + lcb;
    const uint32_t sB = sb + 18432 + lrow * 144 + lcb;

    const int nsteps = K >> 6;

    #pragma unroll
    for (int s = 0; s < 2; s++) {
        const uint32_t o = s * 36864;
        #pragma unroll
        for (int g = 0; g < 4; g++) {
            cp_async16(sA + o + g * 16, Ag + s * 64 + g * 8);
            cp_async16(sB + o + g * 16, Bg + s * 64 + g * 8);
        }
        cp_commit();
    }

    const uint32_t aoff = (uint32_t)((warp_m * 64 + ((quad & 1) << 3) + li) * 144
                                     + ((quad >> 1) << 4));
    const uint32_t boff = (uint32_t)(18432 + (warp_n * 32 + ((quad & 2) ? 8 : 0) + li) * 144
                                     + ((quad & 1) << 4));

    float acc[4][4][4];
    #pragma unroll
    for (int i = 0; i < 4; i++)
        #pragma unroll
        for (int j = 0; j < 4; j++)
            #pragma unroll
            for (int p = 0; p < 4; p++) acc[i][j][p] = 0.0f;

    for (int s = 0; s < nsteps; s++) {
        if (s + 1 < nsteps) cp_wait<1>(); else cp_wait<0>();
        __syncthreads();
        if (s + 2 < nsteps) {
            const uint32_t o = ((s + 2) % 3) * 36864;
            #pragma unroll
            for (int g = 0; g < 4; g++) {
                cp_async16(sA + o + g * 16, Ag + (s + 2) * 64 + g * 8);
                cp_async16(sB + o + g * 16, Bg + (s + 2) * 64 + g * 8);
            }
            cp_commit();
        }
        const uint32_t stg = sb + (s % 3) * 36864;

        #pragma unroll
        for (int ks = 0; ks < 4; ks++) {
            uint32_t af[4][4];
            #pragma unroll
            for (int i = 0; i < 4; i++)
                ldsm_x4(af[i], stg + aoff + i * 2304 + ks * 32);
            #pragma unroll
            for (int j2 = 0; j2 < 2; j2++) {
                uint32_t bf[4];
                ldsm_x4(bf, stg + boff + j2 * 2304 + ks * 32);
                #pragma unroll
                for (int i = 0; i < 4; i++) {
                    mma_f16(acc[i][2 * j2],     af[i], bf);
                    mma_f16(acc[i][2 * j2 + 1], af[i], bf + 2);
                }
            }
        }
    }

    #pragma unroll
    for (int i = 0; i < 4; i++) {
        #pragma unroll
        for (int j = 0; j < 4; j++) {
            int gr0 = bm + warp_m * 64 + i * 16 + r;
            int gc  = bn + warp_n * 32 + j * 8 + cf * 2;
            float v00 = acc[i][j][0] + bias[gc];
            float v01 = acc[i][j][1] + bias[gc + 1];
            float v10 = acc[i][j][2] + bias[gc];
            float v11 = acc[i][j][3] + bias[gc + 1];
            if (GELU) {
                v00 = 0.5f * v00 * (1.0f + erff(v00 * 0.7071067811865476f));
                v01 = 0.5f * v01 * (1.0f + erff(v01 * 0.7071067811865476f));
                v10 = 0.5f * v10 * (1.0f + erff(v10 * 0.7071067811865476f));
                v11 = 0.5f * v11 * (1.0f + erff(v11 * 0.7071067811865476f));
            }
            *(__half2*)(C + (size_t)gr0 * N + gc)       = __floats2half2_rn(v00, v01);
            *(__half2*)(C + (size_t)(gr0 + 8) * N + gc) = __floats2half2_rn(v10, v11);
        }
    }
}

// =====================================================================
// FP16 GEMM + fused LayerNorm epilogue (R10 config). Tile 128x256, BK=64.
// =====================================================================
#define HGEMM_LN_SMEM (3 * 55296)

template<int MODE>
__global__ void __launch_bounds__(512, 1)
hgemm_ln(const __half* __restrict__ A, const __half* __restrict__ Bt,
         const float* __restrict__ bias, const float* __restrict__ resid,
         __half* __restrict__ Ch, float* __restrict__ x,
         __half* __restrict__ xt, float* __restrict__ total, int K)
{
    extern __shared__ char smem[];
    const uint32_t sb = smem_u32(smem);
    const int N = 256;

    const int tid  = threadIdx.x;
    const int lane = tid & 31;
    const int wid  = tid >> 5;
    const int warp_m = wid & 1;
    const int warp_n = wid >> 1;           // 0..7
    const int r  = lane >> 2;
    const int cf = lane & 3;
    const int quad = lane >> 3, li = lane & 7;

    const int bm = blockIdx.x << 7;

    const int ar0 = tid >> 3,           ac0 = (tid & 7) * 16;
    const int ar1 = (tid + 512) >> 3;
    const __half* Ag0 = A + (size_t)(bm + ar0) * K + (ac0 >> 1);
    const __half* Ag1 = A + (size_t)(bm + ar1) * K + (ac0 >> 1);
    const uint32_t sA0 = sb + ar0 * 144 + ac0;
    const uint32_t sA1 = sb + ar1 * 144 + ac0;

    const int nsteps = K >> 6;

    #pragma unroll
    for (int s = 0; s < 2; s++) {
        const uint32_t o = s * 55296;
        cp_async16(sA0 + o, Ag0 + s * 64);
        cp_async16(sA1 + o, Ag1 + s * 64);
        #pragma unroll
        for (int i = 0; i < 4; i++) {
            int c = tid + i * 512;
            int br = c >> 3, bc = (c & 7) * 16;
            cp_async16(sb + 18432 + br * 144 + bc + o,
                       Bt + (size_t)br * K + s * 64 + (bc >> 1));
        }
        cp_commit();
    }

    const uint32_t aoff = (uint32_t)((warp_m * 64 + ((quad & 1) << 3) + li) * 144
                                     + ((quad >> 1) << 4));
    const uint32_t boff = (uint32_t)(18432 + (warp_n * 32 + ((quad & 2) ? 8 : 0) + li) * 144
                                     + ((quad & 1) << 4));

    float acc[4][4][4];
    #pragma unroll
    for (int i = 0; i < 4; i++)
        #pragma unroll
        for (int j = 0; j < 4; j++)
            #pragma unroll
            for (int p = 0; p < 4; p++) acc[i][j][p] = 0.0f;

    for (int s = 0; s < nsteps; s++) {
        if (s + 1 < nsteps) cp_wait<1>(); else cp_wait<0>();
        __syncthreads();
        if (s + 2 < nsteps) {
            const uint32_t o = ((s + 2) % 3) * 55296;
            cp_async16(sA0 + o, Ag0 + (s + 2) * 64);
            cp_async16(sA1 + o, Ag1 + (s + 2) * 64);
            #pragma unroll
            for (int i = 0; i < 4; i++) {
                int c = tid + i * 512;
                int br = c >> 3, bc = (c & 7) * 16;
                cp_async16(sb + 18432 + br * 144 + bc + o,
                           Bt + (size_t)br * K + (s + 2) * 64 + (bc >> 1));
            }
            cp_commit();
        }
        const uint32_t stg = sb + (s % 3) * 55296;

        #pragma unroll
        for (int ks = 0; ks < 4; ks++) {
            uint32_t af[4][4];
            #pragma unroll
            for (int i = 0; i < 4; i++)
                ldsm_x4(af[i], stg + aoff + i * 2304 + ks * 32);
            #pragma unroll
            for (int j2 = 0; j2 < 2; j2++) {
                uint32_t bf[4];
                ldsm_x4(bf, stg + boff + j2 * 2304 + ks * 32);
                #pragma unroll
                for (int i = 0; i < 4; i++) {
                    mma_f16(acc[i][2 * j2],     af[i], bf);
                    mma_f16(acc[i][2 * j2 + 1], af[i], bf + 2);
                }
            }
        }
    }
    __syncthreads();   // smem free -> LN buffers

    #pragma unroll
    for (int i = 0; i < 4; i++) {
        int gr0 = bm + warp_m * 64 + i * 16 + r;
        #pragma unroll
        for (int j = 0; j < 4; j++) {
            int gc = warp_n * 32 + j * 8 + cf * 2;
            float b0 = bias[gc], b1 = bias[gc + 1];
            acc[i][j][0] += b0; acc[i][j][1] += b1;
            acc[i][j][2] += b0; acc[i][j][3] += b1;
            if (MODE == 1) {
                acc[i][j][0] += resid[(size_t)gr0 * N + gc];
                acc[i][j][1] += resid[(size_t)gr0 * N + gc + 1];
                acc[i][j][2] += resid[(size_t)(gr0 + 8) * N + gc];
                acc[i][j][3] += resid[(size_t)(gr0 + 8) * N + gc + 1];
            }
        }
    }

    float* redA = (float*)smem;
    float* redB = (float*)(smem + 4096);
    #pragma unroll
    for (int i = 0; i < 4; i++) {
        float s_lo = 0.0f, s_hi = 0.0f;
        #pragma unroll
        for (int j = 0; j < 4; j++) {
            s_lo += acc[i][j][0] + acc[i][j][1];
            s_hi += acc[i][j][2] + acc[i][j][3];
        }
        s_lo += __shfl_xor_sync(0xFFFFFFFFu, s_lo, 1);
        s_lo += __shfl_xor_sync(0xFFFFFFFFu, s_lo, 2);
        s_hi += __shfl_xor_sync(0xFFFFFFFFu, s_hi, 1);
        s_hi += __shfl_xor_sync(0xFFFFFFFFu, s_hi, 2);
        if (cf == 0) {
            int rl = warp_m * 64 + i * 16 + r;
            redA[rl * 8 + warp_n]       = s_lo;
            redA[(rl + 8) * 8 + warp_n] = s_hi;
        }
    }
    __syncthreads();
    float mu[4][2];
    #pragma unroll
    for (int i = 0; i < 4; i++) {
        int rl = warp_m * 64 + i * 16 + r;
        float a = 0.0f, b = 0.0f;
        #pragma unroll
        for (int w = 0; w < 8; w++) { a += redA[rl * 8 + w]; b += redA[(rl + 8) * 8 + w]; }
        mu[i][0] = a * (1.0f / 256.0f);
        mu[i][1] = b * (1.0f / 256.0f);
    }

    #pragma unroll
    for (int i = 0; i < 4; i++) {
        float s_lo = 0.0f, s_hi = 0.0f;
        #pragma unroll
        for (int j = 0; j < 4; j++) {
            float d0 = acc[i][j][0] - mu[i][0], d1 = acc[i][j][1] - mu[i][0];
            float d2 = acc[i][j][2] - mu[i][1], d3 = acc[i][j][3] - mu[i][1];
            s_lo += d0 * d0 + d1 * d1;
            s_hi += d2 * d2 + d3 * d3;
        }
        s_lo += __shfl_xor_sync(0xFFFFFFFFu, s_lo, 1);
        s_lo += __shfl_xor_sync(0xFFFFFFFFu, s_lo, 2);
        s_hi += __shfl_xor_sync(0xFFFFFFFFu, s_hi, 1);
        s_hi += __shfl_xor_sync(0xFFFFFFFFu, s_hi, 2);
        if (cf == 0) {
            int rl = warp_m * 64 + i * 16 + r;
            redB[rl * 8 + warp_n]       = s_lo;
            redB[(rl + 8) * 8 + warp_n] = s_hi;
        }
    }
    __syncthreads();

    #pragma unroll
    for (int i = 0; i < 4; i++) {
        int rl = warp_m * 64 + i * 16 + r;
        float a = 0.0f, b = 0.0f;
        #pragma unroll
        for (int w = 0; w < 8; w++) { a += redB[rl * 8 + w]; b += redB[(rl + 8) * 8 + w]; }
        float rs_lo = rsqrtf(a * (1.0f / 256.0f) + 1e-5f);
        float rs_hi = rsqrtf(b * (1.0f / 256.0f) + 1e-5f);
        int gr0 = bm + rl;
        #pragma unroll
        for (int j = 0; j < 4; j++) {
            int gc = warp_n * 32 + j * 8 + cf * 2;
            float o00 = (acc[i][j][0] - mu[i][0]) * rs_lo;
            float o01 = (acc[i][j][1] - mu[i][0]) * rs_lo;
            float o10 = (acc[i][j][2] - mu[i][1]) * rs_hi;
            float o11 = (acc[i][j][3] - mu[i][1]) * rs_hi;
            if (MODE == 1) {
                *(__half2*)(Ch + (size_t)gr0 * N + gc)       = __floats2half2_rn(o00, o01);
                *(__half2*)(Ch + (size_t)(gr0 + 8) * N + gc) = __floats2half2_rn(o10, o11);
            } else {
                size_t i0 = (size_t)gr0 * N + gc;
                size_t i1 = (size_t)(gr0 + 8) * N + gc;
                *(float2*)(x + i0) = make_float2(o00, o01);
                *(float2*)(x + i1) = make_float2(o10, o11);
                float2 t0 = *(float2*)(total + i0);
                float2 t1 = *(float2*)(total + i1);
                t0.x += o00; t0.y += o01; t1.x += o10; t1.y += o11;
                *(float2*)(total + i0) = t0;
                *(float2*)(total + i1) = t1;
                *(__half2*)(xt + i0) = __floats2half2_rn(o00, o01);
                *(__half2*)(xt + i1) = __floats2half2_rn(o10, o11);
            }
        }
    }
}

// =====================================================================
// Fused FP16 attention, FA2-style: probs stay in registers (score C-frag
// == PV A-frag), PV k-split across wn halves + smem fp32 reduction.
// smem: Qs 9216 | KV 36864 | R2 17408 | red 1024 | ids 1024 = 65536
// =====================================================================
#define ATTN_SMEM_BYTES 65536

__global__ void __launch_bounds__(256, 2)
attn_fused(const __half* __restrict__ qkv, const int* __restrict__ ids,
           __half* __restrict__ ctxt)
{
    extern __shared__ char sm[];
    char* Qs = sm;                         // 9216 B
    char* KV = sm + 9216;                  // 36864 B (K then V)
    float* R2   = (float*)(sm + 46080);    // [4 wm][16][68] fp32 partials
    float* red  = (float*)(sm + 63488);    // [2][64][2]
    int*   ids_s = (int*)(sm + 64512);

    const int tid  = threadIdx.x;
    const int lane = tid & 31;
    const int wid  = tid >> 5;
    const int r  = lane >> 2;
    const int cf = lane & 3;
    const int quad = lane >> 3, li = lane & 7;

    const int qb = blockIdx.x;
    const int bh = blockIdx.y;
    const int b  = bh >> 2, h = bh & 3;

    const __half* Qg = qkv + ((size_t)b * SS + qb * 64) * QKVN + h * DHH;
    const __half* Kg = qkv + (size_t)b * SS * QKVN + 256 + h * DHH;
    const __half* Vg = qkv + (size_t)b * SS * QKVN + 512 + h * DHH;
    __half* Cg = ctxt + (size_t)b * SS * DD + h * DHH + (size_t)qb * 64 * DD;
    const int* idb = ids + b * SS;

    ids_s[tid] = idb[tid];

    {
        int row = tid >> 2, c = (tid & 3) * 32;
        const __half* src = Qg + (size_t)row * QKVN + (c >> 1);
        *(float4*)(Qs + row * 144 + c)      = *(const float4*)(src);
        *(float4*)(Qs + row * 144 + c + 16) = *(const float4*)(src + 8);
    }
    #pragma unroll
    for (int rp = 0; rp < 4; rp++) {
        int row = (tid >> 2) + rp * 64, c = (tid & 3) * 32;
        const __half* src = Kg + (size_t)row * QKVN + (c >> 1);
        *(float4*)(KV + row * 144 + c)      = *(const float4*)(src);
        *(float4*)(KV + row * 144 + c + 16) = *(const float4*)(src + 8);
    }
    __syncthreads();

    const int wm = wid & 3, wn = wid >> 2;        // wm 0..3, wn 0..1
    const uint32_t sbQ = smem_u32(Qs);
    const uint32_t sbK = smem_u32(KV);

    // ---- scores: rows wm*16..+15, cols wn*128..+127 ----
    float acc[16][4];
    #pragma unroll
    for (int j = 0; j < 16; j++)
        #pragma unroll
        for (int p = 0; p < 4; p++) acc[j][p] = 0.0f;

    {
        uint32_t qa[4][4];
        const uint32_t qoff = sbQ + (wm * 16 + ((quad & 1) << 3) + li) * 144
                              + ((quad >> 1) << 4);
        #pragma unroll
        for (int ks = 0; ks < 4; ks++) ldsm_x4(qa[ks], qoff + ks * 32);

        const uint32_t koff = sbK + (((quad & 2) ? 8 : 0) + li) * 144 + ((quad & 1) << 4);
        #pragma unroll
        for (int j2 = 0; j2 < 8; j2++) {
            #pragma unroll
            for (int ks = 0; ks < 4; ks++) {
                uint32_t bf[4];
                ldsm_x4(bf, koff + (wn * 128 + j2 * 16) * 144 + ks * 32);
                mma_f16(acc[2 * j2],     qa[ks], bf);
                mma_f16(acc[2 * j2 + 1], qa[ks], bf + 2);
            }
        }
    }

    // ---- mask/scale + softmax (fp32, regs); V prefetch overlapped ----
    uint32_t pa[8][4];     // PV A-fragments (half2 packed), kk = 0..7
    {
        const int row_lo = qb * 64 + wm * 16 + r;
        const int row_hi = row_lo + 8;
        float mlo = -1e30f, mhi = -1e30f;
        #pragma unroll
        for (int j = 0; j < 16; j++) {
            int gc = wn * 128 + j * 8 + cf * 2;
            bool ok0 = ids_s[gc] > 0, ok1 = ids_s[gc + 1] > 0;
            acc[j][0] = acc[j][0] * 0.125f + ((ok0 && gc     <= row_lo) ? 0.0f : -10000.0f);
            acc[j][1] = acc[j][1] * 0.125f + ((ok1 && gc + 1 <= row_lo) ? 0.0f : -10000.0f);
            acc[j][2] = acc[j][2] * 0.125f + ((ok0 && gc     <= row_hi) ? 0.0f : -10000.0f);
            acc[j][3] = acc[j][3] * 0.125f + ((ok1 && gc + 1 <= row_hi) ? 0.0f : -10000.0f);
            mlo = fmaxf(mlo, fmaxf(acc[j][0], acc[j][1]));
            mhi = fmaxf(mhi, fmaxf(acc[j][2], acc[j][3]));
        }
        mlo = fmaxf(mlo, __shfl_xor_sync(0xFFFFFFFFu, mlo, 1));
        mlo = fmaxf(mlo, __shfl_xor_sync(0xFFFFFFFFu, mlo, 2));
        mhi = fmaxf(mhi, __shfl_xor_sync(0xFFFFFFFFu, mhi, 1));
        mhi = fmaxf(mhi, __shfl_xor_sync(0xFFFFFFFFu, mhi, 2));
        if (cf == 0) {
            red[(wm * 16 + r) * 2 + wn]     = mlo;
            red[(wm * 16 + 8 + r) * 2 + wn] = mhi;
        }
        __syncthreads();   // score MMAs done -> K buffer dead

        // prefetch V into KV (overlaps exp/sum)
        {
            int row0 = tid >> 2, c = (tid & 3) * 32;
            #pragma unroll
            for (int rp = 0; rp < 4; rp++) {
                int row = row0 + rp * 64;
                const __half* src = Vg + (size_t)row * QKVN + (c >> 1);
                cp_async16(sbK + row * 144 + c,      src);
                cp_async16(sbK + row * 144 + c + 16, src + 8);
            }
            cp_commit();
        }

        float Mlo = fmaxf(red[(wm * 16 + r) * 2],     red[(wm * 16 + r) * 2 + 1]);
        float Mhi = fmaxf(red[(wm * 16 + 8 + r) * 2], red[(wm * 16 + 8 + r) * 2 + 1]);

        float slo = 0.0f, shi = 0.0f;
        #pragma unroll
        for (int j = 0; j < 16; j++) {
            acc[j][0] = __expf(acc[j][0] - Mlo);
            acc[j][1] = __expf(acc[j][1] - Mlo);
            acc[j][2] = __expf(acc[j][2] - Mhi);
            acc[j][3] = __expf(acc[j][3] - Mhi);
            slo += acc[j][0] + acc[j][1];
            shi += acc[j][2] + acc[j][3];
        }
        slo += __shfl_xor_sync(0xFFFFFFFFu, slo, 1);
        slo += __shfl_xor_sync(0xFFFFFFFFu, slo, 2);
        shi += __shfl_xor_sync(0xFFFFFFFFu, shi, 1);
        shi += __shfl_xor_sync(0xFFFFFFFFu, shi, 2);
        if (cf == 0) {
            red[128 + (wm * 16 + r) * 2 + wn]     = slo;
            red[128 + (wm * 16 + 8 + r) * 2 + wn] = shi;
        }
        __syncthreads();
        float inv_lo = 1.0f / (red[128 + (wm * 16 + r) * 2]     + red[128 + (wm * 16 + r) * 2 + 1]);
        float inv_hi = 1.0f / (red[128 + (wm * 16 + 8 + r) * 2] + red[128 + (wm * 16 + 8 + r) * 2 + 1]);

        // normalize + pack into PV A-fragments (register-only, no smem):
        // kk k-block: a0 = p[2kk][0..1] (row lo), a1 = p[2kk][2..3] (row hi),
        //             a2 = p[2kk+1][0..1] (lo),   a3 = p[2kk+1][2..3] (hi)
        #pragma unroll
        for (int kk = 0; kk < 8; kk++) {
            __half2 h0 = __floats2half2_rn(acc[2*kk][0]   * inv_lo, acc[2*kk][1]   * inv_lo);
            __half2 h1 = __floats2half2_rn(acc[2*kk][2]   * inv_hi, acc[2*kk][3]   * inv_hi);
            __half2 h2 = __floats2half2_rn(acc[2*kk+1][0] * inv_lo, acc[2*kk+1][1] * inv_lo);
            __half2 h3 = __floats2half2_rn(acc[2*kk+1][2] * inv_hi, acc[2*kk+1][3] * inv_hi);
            pa[kk][0] = *(uint32_t*)&h0;
            pa[kk][1] = *(uint32_t*)&h1;
            pa[kk][2] = *(uint32_t*)&h2;
            pa[kk][3] = *(uint32_t*)&h3;
        }
    }
    cp_wait<0>();
    __syncthreads();   // V arrived

    // ---- PV: warp covers k in [wn*128, wn*128+128), all 64 cols ----
    {
        float acc2[8][4];
        #pragma unroll
        for (int j = 0; j < 8; j++)
            #pragma unroll
            for (int p = 0; p < 4; p++) acc2[j][p] = 0.0f;

        const int vrow_l = ((quad & 1) << 3) + li;
        const int vcol_l = ((quad >> 1) << 3);

        #pragma unroll
        for (int kk = 0; kk < 8; kk++) {
            int kglob = wn * 128 + kk * 16;
            #pragma unroll
            for (int j2 = 0; j2 < 4; j2++) {
                uint32_t vb[4];
                ldsm_x4_t(vb, sbK + (kglob + vrow_l) * 144
                              + (j2 * 16 + vcol_l) * 2);
                mma_f16(acc2[2 * j2],     pa[kk], vb);
                mma_f16(acc2[2 * j2 + 1], pa[kk], vb + 2);
            }
        }

        // cross-warp k-reduction: wn==1 stores partials, wn==0 adds + writes
        float* mybuf = R2 + wm * (16 * 68);
        if (wn == 1) {
            #pragma unroll
            for (int j = 0; j < 8; j++) {
                int col = j * 8 + cf * 2;
                *(float2*)&mybuf[r * 68 + col]       = make_float2(acc2[j][0], acc2[j][1]);
                *(float2*)&mybuf[(r + 8) * 68 + col] = make_float2(acc2[j][2], acc2[j][3]);
            }
        }
        __syncthreads();
        if (wn == 0) {
            #pragma unroll
            for (int j = 0; j < 8; j++) {
                int col = j * 8 + cf * 2;
                float2 t0 = *(float2*)&mybuf[r * 68 + col];
                float2 t1 = *(float2*)&mybuf[(r + 8) * 68 + col];
                int lrow = wm * 16 + r;
                *(__half2*)(Cg + (size_t)lrow * DD + col) =
                    __floats2half2_rn(acc2[j][0] + t0.x, acc2[j][1] + t0.y);
                *(__half2*)(Cg + (size_t)(lrow + 8) * DD + col) =
                    __floats2half2_rn(acc2[j][2] + t1.x, acc2[j][3] + t1.y);
            }
        }
    }
}

// ---------------- host orchestration ----------------
extern "C" void kernel_launch(void* const* d_in, const int* in_sizes, int n_in,
                              void* d_out, int out_size) {
    const int*   ids      = (const int*)  d_in[0];
    const float* item_emb = (const float*)d_in[1];
    const float* pos_emb  = (const float*)d_in[2];
    const float* Wq = (const float*)d_in[3];
    const float* bq = (const float*)d_in[4];
    const float* Wk = (const float*)d_in[5];
    const float* bk = (const float*)d_in[6];
    const float* Wv = (const float*)d_in[7];
    const float* bv = (const float*)d_in[8];
    const float* Wo = (const float*)d_in[9];
    const float* bo = (const float*)d_in[10];
    const float* W1 = (const float*)d_in[11];
    const float* b1 = (const float*)d_in[12];
    const float* W2 = (const float*)d_in[13];
    const float* b2 = (const float*)d_in[14];
    float* out = (float*)d_out;

    float *x, *bqkv;
    __half *xt, *qkv, *ctxt, *ht, *midt, *wt;
    cudaGetSymbolAddress((void**)&x,    g_x);
    cudaGetSymbolAddress((void**)&xt,   g_xt);
    cudaGetSymbolAddress((void**)&qkv,  g_qkv);
    cudaGetSymbolAddress((void**)&ctxt, g_ctxt);
    cudaGetSymbolAddress((void**)&ht,   g_ht);
    cudaGetSymbolAddress((void**)&midt, g_midt);
    cudaGetSymbolAddress((void**)&wt,   g_wt);
    cudaGetSymbolAddress((void**)&bqkv, g_bqkv);

    cudaFuncSetAttribute(attn_fused, cudaFuncAttributeMaxDynamicSharedMemorySize,
                         ATTN_SMEM_BYTES);
    cudaFuncSetAttribute(hgemm<0>, cudaFuncAttributeMaxDynamicSharedMemorySize, HGEMM_SMEM);
    cudaFuncSetAttribute(hgemm<1>, cudaFuncAttributeMaxDynamicSharedMemorySize, HGEMM_SMEM);
    cudaFuncSetAttribute(hgemm_ln<1>, cudaFuncAttributeMaxDynamicSharedMemorySize, HGEMM_LN_SMEM);
    cudaFuncSetAttribute(hgemm_ln<2>, cudaFuncAttributeMaxDynamicSharedMemorySize, HGEMM_LN_SMEM);

    conv_all<<<(LL * 786432 + 255) / 256, 256>>>(Wq, Wk, Wv, Wo, W1, W2, wt);
    {
        dim3 g(3, LL);
        concat_bias<<<g, 256>>>(bq, bk, bv, bqkv);
    }
    embed_ln_kernel<<<MM, 256>>>(ids, item_emb, pos_emb, x, xt, out);

    dim3 gQKV(QKVN / 128, MM / 128);    // (6, 512)
    dim3 gFF1(FF / 128, MM / 128);      // (8, 512)
    dim3 gAttn(SS / 64, BB * HH);       // (4, 1024)

    for (int l = 0; l < LL; l++) {
        __half* base = wt + (size_t)l * 786432;
        const __half* Wqkvt = base;
        const __half* Wot   = base + 196608;
        const __half* W1t   = base + 262144;
        const __half* W2t   = base + 524288;

        hgemm<0><<<gQKV, 256, HGEMM_SMEM>>>(xt, Wqkvt, bqkv + l * QKVN, qkv, DD, QKVN);

        attn_fused<<<gAttn, 256, ATTN_SMEM_BYTES>>>(qkv, ids, ctxt);

        hgemm_ln<1><<<MM / 128, 512, HGEMM_LN_SMEM>>>(
            ctxt, Wot, bo + l * DD, x, ht, nullptr, nullptr, nullptr, DD);

        hgemm<1><<<gFF1, 256, HGEMM_SMEM>>>(ht, W1t, b1 + l * FF, midt, DD, FF);

        hgemm_ln<2><<<MM / 128, 512, HGEMM_LN_SMEM>>>(
            midt, W2t, b2 + l * DD, nullptr, nullptr, x, xt, out, FF);
    }
}